// round 1
// baseline (speedup 1.0000x reference)
#include <cuda_runtime.h>

#define T_STEPS 256
#define HH 512
#define WW 512
#define TILE 32
#define SMW 36            // tile + 2*2 halo
#define SMSTRIDE 40       // padded row stride (floats): keeps float4 alignment, spreads banks

#define ALPHA_LIF 0.85f
#define V_TH      2.0f
#define ALPHA_LI  0.9f

__global__ __launch_bounds__(256, 2)
void snn_fused_kernel(const float* __restrict__ x,
                      const float* __restrict__ kw,
                      float* __restrict__ out) {
    __shared__ float sm[SMW * SMSTRIDE];

    const int tid = threadIdx.x;
    const int tx  = tid & 7;     // 0..7   -> 4 px each => 32 px wide
    const int ty  = tid >> 3;    // 0..31  -> 32 rows
    const int gx0 = blockIdx.x * TILE;
    const int gy0 = blockIdx.y * TILE;

    // conv weights -> registers (uniform, L2/L1 broadcast)
    float w[25];
#pragma unroll
    for (int i = 0; i < 25; i++) w[i] = __ldg(&kw[i]);

    // Precompute cooperative staging offsets: 36x36 = 1296 elems, <=6 per thread.
    int gsrc[6];
    int sdst[6];
#pragma unroll
    for (int j = 0; j < 6; j++) {
        int i = tid + j * 256;
        if (i < SMW * SMW) {
            int r = i / SMW;
            int c = i - r * SMW;
            int gy = gy0 - 2 + r;
            int gx = gx0 - 2 + c;
            bool ok = ((unsigned)gy < (unsigned)HH) && ((unsigned)gx < (unsigned)WW);
            gsrc[j] = ok ? (gy * WW + gx) : -1;
            sdst[j] = r * SMSTRIDE + c;
        } else {
            gsrc[j] = -1;
            sdst[j] = -1;
        }
    }

    // per-pixel LIF / LI state (4 horizontally adjacent pixels)
    float s1a = 0.f, s1b = 0.f, s1c = 0.f, s1d = 0.f;
    float s2a = 0.f, s2b = 0.f, s2c = 0.f, s2d = 0.f;

    const int orow = (gy0 + ty) * WW + gx0 + tx * 4;
    const float* xt = x;
    float*       ot = out + orow;

    for (int t = 0; t < T_STEPS; t++) {
        // stage tile + halo
#pragma unroll
        for (int j = 0; j < 6; j++) {
            if (sdst[j] >= 0) {
                float v = (gsrc[j] >= 0) ? xt[gsrc[j]] : 0.0f;
                sm[sdst[j]] = v;
            }
        }
        __syncthreads();

        // 5x5 conv for 4 adjacent output px via two float4 smem loads per row
        float a0 = 0.f, a1 = 0.f, a2 = 0.f, a3 = 0.f;
#pragma unroll
        for (int r = 0; r < 5; r++) {
            const float* rp = &sm[(ty + r) * SMSTRIDE + tx * 4];
            float4 va = *(const float4*)rp;
            float4 vb = *(const float4*)(rp + 4);
            float w0 = w[r * 5 + 0], w1 = w[r * 5 + 1], w2 = w[r * 5 + 2],
                  w3 = w[r * 5 + 3], w4 = w[r * 5 + 4];
            a0 = fmaf(w0, va.x, a0); a1 = fmaf(w0, va.y, a1);
            a2 = fmaf(w0, va.z, a2); a3 = fmaf(w0, va.w, a3);
            a0 = fmaf(w1, va.y, a0); a1 = fmaf(w1, va.z, a1);
            a2 = fmaf(w1, va.w, a2); a3 = fmaf(w1, vb.x, a3);
            a0 = fmaf(w2, va.z, a0); a1 = fmaf(w2, va.w, a1);
            a2 = fmaf(w2, vb.x, a2); a3 = fmaf(w2, vb.y, a3);
            a0 = fmaf(w3, va.w, a0); a1 = fmaf(w3, vb.x, a1);
            a2 = fmaf(w3, vb.y, a2); a3 = fmaf(w3, vb.z, a3);
            a0 = fmaf(w4, vb.x, a0); a1 = fmaf(w4, vb.y, a1);
            a2 = fmaf(w4, vb.z, a2); a3 = fmaf(w4, vb.w, a3);
        }

        // FastLIF (soft reset) + FastLI readout
        float v0 = fmaf(ALPHA_LIF, s1a, a0);
        float v1 = fmaf(ALPHA_LIF, s1b, a1);
        float v2 = fmaf(ALPHA_LIF, s1c, a2);
        float v3 = fmaf(ALPHA_LIF, s1d, a3);
        float k0 = (v0 >= V_TH) ? 1.0f : 0.0f;
        float k1 = (v1 >= V_TH) ? 1.0f : 0.0f;
        float k2 = (v2 >= V_TH) ? 1.0f : 0.0f;
        float k3 = (v3 >= V_TH) ? 1.0f : 0.0f;
        s1a = fmaf(k0, -V_TH, v0);
        s1b = fmaf(k1, -V_TH, v1);
        s1c = fmaf(k2, -V_TH, v2);
        s1d = fmaf(k3, -V_TH, v3);
        s2a = fmaf(ALPHA_LI, s2a, k0);
        s2b = fmaf(ALPHA_LI, s2b, k1);
        s2c = fmaf(ALPHA_LI, s2c, k2);
        s2d = fmaf(ALPHA_LI, s2d, k3);

        float4 o;
        o.x = s2a; o.y = s2b; o.z = s2c; o.w = s2d;
        *(float4*)ot = o;

        __syncthreads();   // protect smem before next timestep's overwrite
        xt += HH * WW;
        ot += HH * WW;
    }
}

extern "C" void kernel_launch(void* const* d_in, const int* in_sizes, int n_in,
                              void* d_out, int out_size) {
    const float* x  = (const float*)d_in[0];   // [256,1,512,512] f32
    const float* kw = (const float*)d_in[1];   // [1,1,5,5] f32
    float* out = (float*)d_out;                // [256,1,512,512] f32
    (void)in_sizes; (void)n_in; (void)out_size;

    dim3 grid(WW / TILE, HH / TILE);           // 16 x 16 tiles
    dim3 block(256);
    snn_fused_kernel<<<grid, block>>>(x, kw, out);
}

// round 2
// speedup vs baseline: 1.4661x; 1.4661x over previous
#include <cuda_runtime.h>

#define T_STEPS 256
#define HH 512
#define WW 512
#define TILE 32
#define SMW 36            // tile + 2*2 halo
#define SMSTRIDE 40       // padded row stride (floats)

#define ALPHA_LIF 0.85f
#define V_TH      2.0f
#define ALPHA_LI  0.9f

__global__ __launch_bounds__(256, 2)
void snn_fused_kernel(const float* __restrict__ x,
                      const float* __restrict__ kw,
                      float* __restrict__ out) {
    __shared__ float sm[2][SMW * SMSTRIDE];

    const int tid = threadIdx.x;
    const int tx  = tid & 7;     // 0..7   -> 4 px each => 32 px wide
    const int ty  = tid >> 3;    // 0..31  -> 32 rows
    const int gx0 = blockIdx.x * TILE;
    const int gy0 = blockIdx.y * TILE;

    // conv weights -> registers
    float w[25];
#pragma unroll
    for (int i = 0; i < 25; i++) w[i] = __ldg(&kw[i]);

    // Cooperative staging map: 36x36 = 1296 elems, <=6 per thread.
    int gsrc[6];
    int sdst[6];
#pragma unroll
    for (int j = 0; j < 6; j++) {
        int i = tid + j * 256;
        if (i < SMW * SMW) {
            int r = i / SMW;
            int c = i - r * SMW;
            int gy = gy0 - 2 + r;
            int gx = gx0 - 2 + c;
            bool ok = ((unsigned)gy < (unsigned)HH) && ((unsigned)gx < (unsigned)WW);
            gsrc[j] = ok ? (gy * WW + gx) : -1;
            sdst[j] = r * SMSTRIDE + c;
        } else {
            gsrc[j] = -1;
            sdst[j] = -1;
        }
    }

    // per-pixel LIF / LI state (4 horizontally adjacent pixels)
    float s1a = 0.f, s1b = 0.f, s1c = 0.f, s1d = 0.f;
    float s2a = 0.f, s2b = 0.f, s2c = 0.f, s2d = 0.f;

    const int orow = (gy0 + ty) * WW + gx0 + tx * 4;
    const float* xt = x;
    float*       ot = out + orow;

    // ---- prologue: stage timestep 0 into buffer 0 ----
#pragma unroll
    for (int j = 0; j < 6; j++) {
        if (sdst[j] >= 0) {
            float v = (gsrc[j] >= 0) ? xt[gsrc[j]] : 0.0f;
            sm[0][sdst[j]] = v;
        }
    }
    __syncthreads();

    for (int t = 0; t < T_STEPS; t++) {
        const int cur = t & 1;
        const int nxt = cur ^ 1;

        // 1) prefetch t+1 into registers (latency overlaps conv below)
        float pre[6];
        const bool have_next = (t + 1 < T_STEPS);
        const float* xn = xt + HH * WW;
#pragma unroll
        for (int j = 0; j < 6; j++) {
            pre[j] = (have_next && gsrc[j] >= 0) ? xn[gsrc[j]] : 0.0f;
        }

        // 2) 5x5 conv for 4 adjacent output px from current buffer
        float a0 = 0.f, a1 = 0.f, a2 = 0.f, a3 = 0.f;
#pragma unroll
        for (int r = 0; r < 5; r++) {
            const float* rp = &sm[cur][(ty + r) * SMSTRIDE + tx * 4];
            float4 va = *(const float4*)rp;
            float4 vb = *(const float4*)(rp + 4);
            float w0 = w[r * 5 + 0], w1 = w[r * 5 + 1], w2 = w[r * 5 + 2],
                  w3 = w[r * 5 + 3], w4 = w[r * 5 + 4];
            a0 = fmaf(w0, va.x, a0); a1 = fmaf(w0, va.y, a1);
            a2 = fmaf(w0, va.z, a2); a3 = fmaf(w0, va.w, a3);
            a0 = fmaf(w1, va.y, a0); a1 = fmaf(w1, va.z, a1);
            a2 = fmaf(w1, va.w, a2); a3 = fmaf(w1, vb.x, a3);
            a0 = fmaf(w2, va.z, a0); a1 = fmaf(w2, va.w, a1);
            a2 = fmaf(w2, vb.x, a2); a3 = fmaf(w2, vb.y, a3);
            a0 = fmaf(w3, va.w, a0); a1 = fmaf(w3, vb.x, a1);
            a2 = fmaf(w3, vb.y, a2); a3 = fmaf(w3, vb.z, a3);
            a0 = fmaf(w4, vb.x, a0); a1 = fmaf(w4, vb.y, a1);
            a2 = fmaf(w4, vb.z, a2); a3 = fmaf(w4, vb.w, a3);
        }

        // 3) FastLIF (soft reset) + FastLI readout
        float v0 = fmaf(ALPHA_LIF, s1a, a0);
        float v1 = fmaf(ALPHA_LIF, s1b, a1);
        float v2 = fmaf(ALPHA_LIF, s1c, a2);
        float v3 = fmaf(ALPHA_LIF, s1d, a3);
        float k0 = (v0 >= V_TH) ? 1.0f : 0.0f;
        float k1 = (v1 >= V_TH) ? 1.0f : 0.0f;
        float k2 = (v2 >= V_TH) ? 1.0f : 0.0f;
        float k3 = (v3 >= V_TH) ? 1.0f : 0.0f;
        s1a = fmaf(k0, -V_TH, v0);
        s1b = fmaf(k1, -V_TH, v1);
        s1c = fmaf(k2, -V_TH, v2);
        s1d = fmaf(k3, -V_TH, v3);
        s2a = fmaf(ALPHA_LI, s2a, k0);
        s2b = fmaf(ALPHA_LI, s2b, k1);
        s2c = fmaf(ALPHA_LI, s2c, k2);
        s2d = fmaf(ALPHA_LI, s2d, k3);

        float4 o;
        o.x = s2a; o.y = s2b; o.z = s2c; o.w = s2d;
        *(float4*)ot = o;

        // 4) stage prefetched t+1 into the other buffer
#pragma unroll
        for (int j = 0; j < 6; j++) {
            if (sdst[j] >= 0) sm[nxt][sdst[j]] = pre[j];
        }

        // single barrier per timestep
        __syncthreads();

        xt += HH * WW;
        ot += HH * WW;
    }
}

extern "C" void kernel_launch(void* const* d_in, const int* in_sizes, int n_in,
                              void* d_out, int out_size) {
    const float* x  = (const float*)d_in[0];   // [256,1,512,512] f32
    const float* kw = (const float*)d_in[1];   // [1,1,5,5] f32
    float* out = (float*)d_out;                // [256,1,512,512] f32
    (void)in_sizes; (void)n_in; (void)out_size;

    dim3 grid(WW / TILE, HH / TILE);           // 16 x 16 tiles
    dim3 block(256);
    snn_fused_kernel<<<grid, block>>>(x, kw, out);
}

// round 3
// speedup vs baseline: 1.5012x; 1.0239x over previous
#include <cuda_runtime.h>
#include <cstdint>

#define T_STEPS 256
#define HH 512
#define WW 512
#define TILE 32
#define SMW 36            // tile + 2*2 halo
#define SMSTRIDE 40       // padded row stride (floats)
#define STAGE_ELEMS (SMW * SMSTRIDE)

#define ALPHA_LIF 0.85f
#define V_TH      2.0f
#define ALPHA_LI  0.9f

// 4-byte cp.async with zero-fill when pred is false (src-size 0 -> zfill)
__device__ __forceinline__ void cp_async4(float* smem_dst, const float* gsrc, bool pred) {
    uint32_t s = (uint32_t)__cvta_generic_to_shared(smem_dst);
    int srcsz = pred ? 4 : 0;
    asm volatile("cp.async.ca.shared.global [%0], [%1], 4, %2;\n"
                 :: "r"(s), "l"(gsrc), "r"(srcsz));
}
__device__ __forceinline__ void cp_async_commit() {
    asm volatile("cp.async.commit_group;\n" ::: "memory");
}
__device__ __forceinline__ void cp_async_wait1() {
    asm volatile("cp.async.wait_group 1;\n" ::: "memory");
}

__global__ __launch_bounds__(256, 2)
void snn_fused_kernel(const float* __restrict__ x,
                      const float* __restrict__ kw,
                      float* __restrict__ out) {
    __shared__ float sm[3][STAGE_ELEMS];

    const int tid = threadIdx.x;
    const int tx  = tid & 7;     // 0..7   -> 4 px each => 32 px wide
    const int ty  = tid >> 3;    // 0..31  -> 32 rows
    const int gx0 = blockIdx.x * TILE;
    const int gy0 = blockIdx.y * TILE;

    // conv weights -> registers
    float w[25];
#pragma unroll
    for (int i = 0; i < 25; i++) w[i] = __ldg(&kw[i]);

    // Cooperative staging map: 36x36 = 1296 elems, <=6 per thread.
    int  goff[6];     // spatial offset within a frame (0 when OOB, guarded by gok)
    int  sdst[6];     // smem float index, -1 if unused slot
    bool gok[6];
#pragma unroll
    for (int j = 0; j < 6; j++) {
        int i = tid + j * 256;
        if (i < SMW * SMW) {
            int r = i / SMW;
            int c = i - r * SMW;
            int gy = gy0 - 2 + r;
            int gx = gx0 - 2 + c;
            bool ok = ((unsigned)gy < (unsigned)HH) && ((unsigned)gx < (unsigned)WW);
            gok[j]  = ok;
            goff[j] = ok ? (gy * WW + gx) : 0;
            sdst[j] = r * SMSTRIDE + c;
        } else {
            gok[j]  = false;
            goff[j] = 0;
            sdst[j] = -1;
        }
    }

    // ---- prologue: stage t=0 and t=1 via cp.async ----
#pragma unroll
    for (int j = 0; j < 6; j++)
        if (sdst[j] >= 0) cp_async4(&sm[0][sdst[j]], &x[goff[j]], gok[j]);
    cp_async_commit();
#pragma unroll
    for (int j = 0; j < 6; j++)
        if (sdst[j] >= 0) cp_async4(&sm[1][sdst[j]], &x[goff[j] + HH * WW], gok[j]);
    cp_async_commit();

    // per-pixel LIF / LI state (4 horizontally adjacent pixels)
    float s1a = 0.f, s1b = 0.f, s1c = 0.f, s1d = 0.f;
    float s2a = 0.f, s2b = 0.f, s2c = 0.f, s2d = 0.f;

    const int orow = (gy0 + ty) * WW + gx0 + tx * 4;
    float* ot = out + orow;
    const float* xfut = x + 2 * HH * WW;   // frame t+2 base

    int cur = 0;

    for (int t = 0; t < T_STEPS; t++) {
        // group t complete (issued 2 steps ago); allow newest group pending
        cp_async_wait1();
        __syncthreads();

        // issue staging for t+2 into the third buffer (empty group is fine at tail)
        int nxt2 = cur + 2; if (nxt2 >= 3) nxt2 -= 3;
        if (t + 2 < T_STEPS) {
#pragma unroll
            for (int j = 0; j < 6; j++)
                if (sdst[j] >= 0) cp_async4(&sm[nxt2][sdst[j]], &xfut[goff[j]], gok[j]);
        }
        cp_async_commit();

        // 5x5 conv for 4 adjacent output px from current buffer
        float a0 = 0.f, a1 = 0.f, a2 = 0.f, a3 = 0.f;
#pragma unroll
        for (int r = 0; r < 5; r++) {
            const float* rp = &sm[cur][(ty + r) * SMSTRIDE + tx * 4];
            float4 va = *(const float4*)rp;
            float4 vb = *(const float4*)(rp + 4);
            float w0 = w[r * 5 + 0], w1 = w[r * 5 + 1], w2 = w[r * 5 + 2],
                  w3 = w[r * 5 + 3], w4 = w[r * 5 + 4];
            a0 = fmaf(w0, va.x, a0); a1 = fmaf(w0, va.y, a1);
            a2 = fmaf(w0, va.z, a2); a3 = fmaf(w0, va.w, a3);
            a0 = fmaf(w1, va.y, a0); a1 = fmaf(w1, va.z, a1);
            a2 = fmaf(w1, va.w, a2); a3 = fmaf(w1, vb.x, a3);
            a0 = fmaf(w2, va.z, a0); a1 = fmaf(w2, va.w, a1);
            a2 = fmaf(w2, vb.x, a2); a3 = fmaf(w2, vb.y, a3);
            a0 = fmaf(w3, va.w, a0); a1 = fmaf(w3, vb.x, a1);
            a2 = fmaf(w3, vb.y, a2); a3 = fmaf(w3, vb.z, a3);
            a0 = fmaf(w4, vb.x, a0); a1 = fmaf(w4, vb.y, a1);
            a2 = fmaf(w4, vb.z, a2); a3 = fmaf(w4, vb.w, a3);
        }

        // FastLIF (soft reset) + FastLI readout
        float v0 = fmaf(ALPHA_LIF, s1a, a0);
        float v1 = fmaf(ALPHA_LIF, s1b, a1);
        float v2 = fmaf(ALPHA_LIF, s1c, a2);
        float v3 = fmaf(ALPHA_LIF, s1d, a3);
        float k0 = (v0 >= V_TH) ? 1.0f : 0.0f;
        float k1 = (v1 >= V_TH) ? 1.0f : 0.0f;
        float k2 = (v2 >= V_TH) ? 1.0f : 0.0f;
        float k3 = (v3 >= V_TH) ? 1.0f : 0.0f;
        s1a = fmaf(k0, -V_TH, v0);
        s1b = fmaf(k1, -V_TH, v1);
        s1c = fmaf(k2, -V_TH, v2);
        s1d = fmaf(k3, -V_TH, v3);
        s2a = fmaf(ALPHA_LI, s2a, k0);
        s2b = fmaf(ALPHA_LI, s2b, k1);
        s2c = fmaf(ALPHA_LI, s2c, k2);
        s2d = fmaf(ALPHA_LI, s2d, k3);

        float4 o;
        o.x = s2a; o.y = s2b; o.z = s2c; o.w = s2d;
        *(float4*)ot = o;

        cur = cur + 1; if (cur >= 3) cur -= 3;
        xfut += HH * WW;
        ot   += HH * WW;
    }
}

extern "C" void kernel_launch(void* const* d_in, const int* in_sizes, int n_in,
                              void* d_out, int out_size) {
    const float* x  = (const float*)d_in[0];   // [256,1,512,512] f32
    const float* kw = (const float*)d_in[1];   // [1,1,5,5] f32
    float* out = (float*)d_out;                // [256,1,512,512] f32
    (void)in_sizes; (void)n_in; (void)out_size;

    dim3 grid(WW / TILE, HH / TILE);           // 16 x 16 tiles
    dim3 block(256);
    snn_fused_kernel<<<grid, block>>>(x, kw, out);
}

// round 4
// speedup vs baseline: 2.3276x; 1.5505x over previous
#include <cuda_runtime.h>
#include <cstdint>

#define T_STEPS 256
#define HH 512
#define WW 512
#define TILE 32
#define SMW 36            // tile + 2*2 halo
#define SMSTRIDE 40       // padded row stride (floats)
#define STAGE_ELEMS (SMW * SMSTRIDE)

#define ALPHA_LIF 0.85f
#define V_TH      2.0f
#define ALPHA_LI  0.9f

typedef unsigned long long u64;

// ---- packed f32x2 helpers (sm_103a FFMA2 path, PTX-only) ----
__device__ __forceinline__ u64 pk(float lo, float hi) {
    u64 r; asm("mov.b64 %0, {%1, %2};" : "=l"(r) : "f"(lo), "f"(hi)); return r;
}
__device__ __forceinline__ void upk(u64 p, float& lo, float& hi) {
    asm("mov.b64 {%0, %1}, %2;" : "=f"(lo), "=f"(hi) : "l"(p));
}
// acc += a*b (lane-wise fp32x2)
__device__ __forceinline__ void ffma2(u64& acc, u64 a, u64 b) {
    asm("fma.rn.f32x2 %0, %1, %2, %0;" : "+l"(acc) : "l"(a), "l"(b));
}
// d = a*b + c
__device__ __forceinline__ u64 ffma2g(u64 a, u64 b, u64 c) {
    u64 d; asm("fma.rn.f32x2 %0, %1, %2, %3;" : "=l"(d) : "l"(a), "l"(b), "l"(c)); return d;
}

// ---- cp.async helpers ----
__device__ __forceinline__ void cp_async4(float* smem_dst, const float* gsrc, bool pred) {
    uint32_t s = (uint32_t)__cvta_generic_to_shared(smem_dst);
    int srcsz = pred ? 4 : 0;
    asm volatile("cp.async.ca.shared.global [%0], [%1], 4, %2;\n"
                 :: "r"(s), "l"(gsrc), "r"(srcsz));
}
__device__ __forceinline__ void cp_async_commit() {
    asm volatile("cp.async.commit_group;\n" ::: "memory");
}
__device__ __forceinline__ void cp_async_wait1() {
    asm volatile("cp.async.wait_group 1;\n" ::: "memory");
}

__global__ __launch_bounds__(256, 2)
void snn_fused_kernel(const float* __restrict__ x,
                      const float* __restrict__ kw,
                      float* __restrict__ out) {
    __shared__ float sm[3][STAGE_ELEMS];

    const int tid = threadIdx.x;
    const int tx  = tid & 7;     // 0..7   -> 4 px each => 32 px wide
    const int ty  = tid >> 3;    // 0..31  -> 32 rows
    const int gx0 = blockIdx.x * TILE;
    const int gy0 = blockIdx.y * TILE;

    // conv weights -> packed (w,w) pairs in registers
    u64 W2[25];
#pragma unroll
    for (int i = 0; i < 25; i++) { float wv = __ldg(&kw[i]); W2[i] = pk(wv, wv); }

    const u64 ALIF2 = pk(ALPHA_LIF, ALPHA_LIF);
    const u64 NTH2  = pk(-V_TH, -V_TH);
    const u64 ALI2  = pk(ALPHA_LI, ALPHA_LI);
    const u64 ZERO2 = pk(0.f, 0.f);

    // Cooperative staging map: 36x36 = 1296 elems, <=6 per thread.
    int  goff[6];
    int  sdst[6];
    bool gok[6];
#pragma unroll
    for (int j = 0; j < 6; j++) {
        int i = tid + j * 256;
        if (i < SMW * SMW) {
            int r = i / SMW;
            int c = i - r * SMW;
            int gy = gy0 - 2 + r;
            int gx = gx0 - 2 + c;
            bool ok = ((unsigned)gy < (unsigned)HH) && ((unsigned)gx < (unsigned)WW);
            gok[j]  = ok;
            goff[j] = ok ? (gy * WW + gx) : 0;
            sdst[j] = r * SMSTRIDE + c;
        } else {
            gok[j]  = false;
            goff[j] = 0;
            sdst[j] = -1;
        }
    }

    // ---- prologue: stage t=0 and t=1 ----
#pragma unroll
    for (int j = 0; j < 6; j++)
        if (sdst[j] >= 0) cp_async4(&sm[0][sdst[j]], &x[goff[j]], gok[j]);
    cp_async_commit();
#pragma unroll
    for (int j = 0; j < 6; j++)
        if (sdst[j] >= 0) cp_async4(&sm[1][sdst[j]], &x[goff[j] + HH * WW], gok[j]);
    cp_async_commit();

    // packed per-pixel LIF / LI state
    u64 S1_01 = ZERO2, S1_23 = ZERO2, S2_01 = ZERO2, S2_23 = ZERO2;

    const int orow = (gy0 + ty) * WW + gx0 + tx * 4;
    float* ot = out + orow;
    const float* xfut = x + 2 * HH * WW;

    int cur = 0;

    for (int t = 0; t < T_STEPS; t++) {
        cp_async_wait1();
        __syncthreads();

        // stage t+2
        int nxt2 = cur + 2; if (nxt2 >= 3) nxt2 -= 3;
        if (t + 2 < T_STEPS) {
#pragma unroll
            for (int j = 0; j < 6; j++)
                if (sdst[j] >= 0) cp_async4(&sm[nxt2][sdst[j]], &xfut[goff[j]], gok[j]);
        }
        cp_async_commit();

        // 5x5 conv for 4 px as 2 packed accumulators
        u64 A01 = ZERO2, A23 = ZERO2;
#pragma unroll
        for (int r = 0; r < 5; r++) {
            const float* rp = &sm[cur][(ty + r) * SMSTRIDE + tx * 4];
            float4 va = *(const float4*)rp;      // x0..x3
            float4 vb = *(const float4*)(rp + 4); // x4..x7

            u64 AP0 = pk(va.x, va.y);   // aligned pairs (likely reg-pair coalesced)
            u64 AP1 = pk(va.z, va.w);
            u64 AP2 = pk(vb.x, vb.y);
            u64 AP3 = pk(vb.z, vb.w);
            u64 P12 = pk(va.y, va.z);   // odd pairs (real packs)
            u64 P34 = pk(va.w, vb.x);
            u64 P56 = pk(vb.y, vb.z);

            // tap order 0..4 per accumulator: same numeric order as scalar version
            ffma2(A01, W2[r*5+0], AP0);
            ffma2(A01, W2[r*5+1], P12);
            ffma2(A01, W2[r*5+2], AP1);
            ffma2(A01, W2[r*5+3], P34);
            ffma2(A01, W2[r*5+4], AP2);

            ffma2(A23, W2[r*5+0], AP1);
            ffma2(A23, W2[r*5+1], P34);
            ffma2(A23, W2[r*5+2], AP2);
            ffma2(A23, W2[r*5+3], P56);
            ffma2(A23, W2[r*5+4], AP3);
        }

        // FastLIF (soft reset) + FastLI, packed
        u64 V01 = ffma2g(ALIF2, S1_01, A01);
        u64 V23 = ffma2g(ALIF2, S1_23, A23);

        float v0, v1, v2, v3;
        upk(V01, v0, v1);
        upk(V23, v2, v3);
        float k0 = (v0 >= V_TH) ? 1.0f : 0.0f;
        float k1 = (v1 >= V_TH) ? 1.0f : 0.0f;
        float k2 = (v2 >= V_TH) ? 1.0f : 0.0f;
        float k3 = (v3 >= V_TH) ? 1.0f : 0.0f;
        u64 K01 = pk(k0, k1);
        u64 K23 = pk(k2, k3);

        S1_01 = ffma2g(K01, NTH2, V01);     // v - k*Vth
        S1_23 = ffma2g(K23, NTH2, V23);
        S2_01 = ffma2g(ALI2, S2_01, K01);   // a_li*s2 + k
        S2_23 = ffma2g(ALI2, S2_23, K23);

        float4 o;
        upk(S2_01, o.x, o.y);
        upk(S2_23, o.z, o.w);
        *(float4*)ot = o;

        cur = cur + 1; if (cur >= 3) cur -= 3;
        xfut += HH * WW;
        ot   += HH * WW;
    }
}

extern "C" void kernel_launch(void* const* d_in, const int* in_sizes, int n_in,
                              void* d_out, int out_size) {
    const float* x  = (const float*)d_in[0];   // [256,1,512,512] f32
    const float* kw = (const float*)d_in[1];   // [1,1,5,5] f32
    float* out = (float*)d_out;                // [256,1,512,512] f32
    (void)in_sizes; (void)n_in; (void)out_size;

    dim3 grid(WW / TILE, HH / TILE);           // 16 x 16 tiles
    dim3 block(256);
    snn_fused_kernel<<<grid, block>>>(x, kw, out);
}